// round 4
// baseline (speedup 1.0000x reference)
#include <cuda_runtime.h>
#include <stdint.h>

#define IN_CH   128
#define OUT_CH  32
#define MAX_N   100000
#define MAX_E   1600000

// Scratch (allocation-free rule: __device__ globals). 16B alignment is
// load-bearing: float4 loads + red.global.add.v4.f32 require it.
__device__ __align__(16) float d_deg [MAX_N];
__device__ __align__(16) float d_dinv[MAX_N];
__device__ __align__(16) float d_g   [MAX_N * OUT_CH];
__device__ __align__(16) float d_s   [MAX_N * OUT_CH];
__device__ __align__(16) float d_z   [MAX_N * OUT_CH];
__device__ int d_src[MAX_E];
__device__ int d_dst[MAX_E];
__device__ int d_is64;

// ------------------------------------------------- K_detect: int64 vs int32?
// Under little-endian int64 with values < 100000, every odd 32-bit word is 0.
// Under int32 random indices, 64 consecutive odd words all-zero is ~impossible.
__global__ void k_detect(const int* __restrict__ ei_w) {
    if (threadIdx.x == 0) {
        int acc = 0;
        for (int t = 0; t < 64; t++) acc |= ei_w[2 * t + 1];
        d_is64 = (acc == 0) ? 1 : 0;
    }
}

// ------------------------------------------------- K0: zero deg
__global__ void k_zero(int n) {
    int i = blockIdx.x * blockDim.x + threadIdx.x;
    if (i < n) d_deg[i] = 0.0f;
}

// ------------------------------------------------- K1: convert + in-degree (fused)
// int64 layout: words[4E], src_e = w[2e], dst_e = w[2E + 2e]
// int32 layout: words[2E], src_e = w[e],  dst_e = w[E + e]
// Writes dense int32 d_src/d_dst and accumulates in-degree in the same pass.
__global__ void k_convert_degree(const int* __restrict__ ei_w, int E) {
    int e = blockIdx.x * blockDim.x + threadIdx.x;
    if (e >= E) return;
    int s, d;
    if (d_is64) {
        s = ei_w[2 * e];
        d = ei_w[2 * E + 2 * e];
    } else {
        s = ei_w[e];
        d = ei_w[E + e];
    }
    d_src[e] = s;
    d_dst[e] = d;
    atomicAdd(&d_deg[d], 1.0f);
}

// ------------------------------------------------- K2: GEMM + dinv scale
// 256 threads/block, 32 rows/block, 8 threads/row, 4 output cols/thread.
// g[i] = dinv[i] * (x[i] @ W); s initialized to g (self-loop folded in).
__global__ void k_gemm(const float* __restrict__ x, const float* __restrict__ W, int n) {
    __shared__ __align__(16) float sW[IN_CH][OUT_CH];   // 16 KB
    __shared__ float sX[32][IN_CH + 1];                 // padded
    int tid = threadIdx.x;
    int rbase = blockIdx.x * 32;

    for (int i = tid; i < IN_CH * OUT_CH; i += 256)
        sW[i / OUT_CH][i % OUT_CH] = W[i];
    for (int i = tid; i < 32 * IN_CH; i += 256) {
        int r = i / IN_CH, c = i % IN_CH;
        int gr = rbase + r;
        sX[r][c] = (gr < n) ? x[(size_t)gr * IN_CH + c] : 0.0f;
    }
    __syncthreads();

    int rl = tid >> 3;        // local row 0..31
    int cg = tid & 7;         // col group 0..7
    float a0 = 0.f, a1 = 0.f, a2 = 0.f, a3 = 0.f;
#pragma unroll
    for (int k = 0; k < IN_CH; k++) {
        float xv = sX[rl][k];
        float4 wv = *(const float4*)&sW[k][cg * 4];
        a0 += xv * wv.x; a1 += xv * wv.y; a2 += xv * wv.z; a3 += xv * wv.w;
    }
    int row = rbase + rl;
    if (row < n) {
        float dinv = rsqrtf(d_deg[row] + 1.0f);   // +1 = self loop
        if (cg == 0) d_dinv[row] = dinv;
        float4 o = make_float4(a0 * dinv, a1 * dinv, a2 * dinv, a3 * dinv);
        int off = row * OUT_CH + cg * 4;
        *(float4*)&d_g[off] = o;
        *(float4*)&d_s[off] = o;   // accumulator starts with self-loop term
    }
}

// ------------------------------------------------- K3: edge scatter
// 8 lanes per edge, 4 edges per warp. Each lane moves one float4 (16B) of the
// 128B message row; accumulate via vector reduction red.global.add.v4.f32.
__global__ void k_scatter(int E) {
    int wid  = (blockIdx.x * blockDim.x + threadIdx.x) >> 5;
    int lane = threadIdx.x & 31;
    int grp  = lane >> 3;     // edge within warp
    int sub  = lane & 7;      // float4 slot within row
    int e = wid * 4 + grp;
    if (e >= E) return;
    int s = d_src[e];
    int d = d_dst[e];
    float4 v = *(const float4*)&d_g[s * OUT_CH + sub * 4];
    float* addr = &d_s[d * OUT_CH + sub * 4];
    asm volatile("red.global.add.v4.f32 [%0], {%1,%2,%3,%4};"
                 :: "l"(addr), "f"(v.x), "f"(v.y), "f"(v.z), "f"(v.w)
                 : "memory");
}

// ------------------------------------------------- K4: z = relu(dinv*s + b)
__global__ void k_activate(const float* __restrict__ b, int n) {
    int i = blockIdx.x * blockDim.x + threadIdx.x;
    if (i < n * OUT_CH) {
        int node = i >> 5;
        int c = i & 31;
        float v = d_dinv[node] * d_s[i] + b[c];
        d_z[i] = v > 0.0f ? v : 0.0f;
    }
}

// ------------------------------------------------- K5: decoder
// 8 lanes per edge: float4 partial dots + xor-shuffle reduce within the group.
__global__ void k_decode(float* __restrict__ out, int E) {
    int wid  = (blockIdx.x * blockDim.x + threadIdx.x) >> 5;
    int lane = threadIdx.x & 31;
    int grp  = lane >> 3;
    int sub  = lane & 7;
    int e = wid * 4 + grp;
    if (e >= E) return;
    int s = d_src[e];
    int d = d_dst[e];
    float4 a = *(const float4*)&d_z[s * OUT_CH + sub * 4];
    float4 c = *(const float4*)&d_z[d * OUT_CH + sub * 4];
    float p = a.x * c.x + a.y * c.y + a.z * c.z + a.w * c.w;
    p += __shfl_xor_sync(0xffffffffu, p, 4);
    p += __shfl_xor_sync(0xffffffffu, p, 2);
    p += __shfl_xor_sync(0xffffffffu, p, 1);
    if (sub == 0) out[e] = 1.0f / (1.0f + __expf(-p));
}

// ------------------------------------------------- launch
extern "C" void kernel_launch(void* const* d_in, const int* in_sizes, int n_in,
                              void* d_out, int out_size) {
    const float* x    = (const float*)d_in[0];
    const int*   ei_w = (const int*)d_in[1];   // edge_index as 32-bit words
    const float* W    = (const float*)d_in[2];
    const float* b    = (const float*)d_in[3];
    float* out = (float*)d_out;

    int n = in_sizes[0] / IN_CH;      // 100000
    int E = in_sizes[1] / 2;          // 1600000 (element count same for i32/i64)

    k_detect        <<<1, 32>>>(ei_w);
    k_zero          <<<(n + 255) / 256, 256>>>(n);
    k_convert_degree<<<(E + 255) / 256, 256>>>(ei_w, E);
    k_gemm          <<<(n + 31) / 32, 256>>>(x, W, n);
    {   // 8 threads per edge
        long long threads = (long long)E * 8;
        k_scatter<<<(int)((threads + 255) / 256), 256>>>(E);
    }
    k_activate      <<<(n * OUT_CH + 255) / 256, 256>>>(b, n);
    {
        long long threads = (long long)E * 8;
        k_decode<<<(int)((threads + 255) / 256), 256>>>(out, E);
    }
}

// round 5
// speedup vs baseline: 1.1033x; 1.1033x over previous
#include <cuda_runtime.h>
#include <stdint.h>

#define IN_CH   128
#define OUT_CH  32
#define MAX_N   100000
#define MAX_E   1600000

// Scratch (allocation-free rule: __device__ globals). 16B alignment is
// load-bearing: float4 loads + red.global.add.v4.f32 require it.
__device__ __align__(16) float d_deg [MAX_N];
__device__ __align__(16) float d_dinv[MAX_N];
__device__ __align__(16) float d_g   [MAX_N * OUT_CH];
__device__ __align__(16) float d_s   [MAX_N * OUT_CH];
__device__ __align__(16) float d_z   [MAX_N * OUT_CH];
__device__ int d_src[MAX_E];
__device__ int d_dst[MAX_E];
__device__ int d_is64;

// ------------------------------------------------- K_detect: int64 vs int32?
// Under little-endian int64 with values < 100000, every odd 32-bit word is 0.
// Under int32 random indices, 64 consecutive odd words all-zero is ~impossible.
__global__ void k_detect(const int* __restrict__ ei_w) {
    if (threadIdx.x == 0) {
        int acc = 0;
        for (int t = 0; t < 64; t++) acc |= ei_w[2 * t + 1];
        d_is64 = (acc == 0) ? 1 : 0;
    }
}

// ------------------------------------------------- K0: zero deg
__global__ void k_zero(int n) {
    int i = blockIdx.x * blockDim.x + threadIdx.x;
    if (i < n) d_deg[i] = 0.0f;
}

// ------------------------------------------------- K1: convert + in-degree (fused)
__global__ void k_convert_degree(const int* __restrict__ ei_w, int E) {
    int e = blockIdx.x * blockDim.x + threadIdx.x;
    if (e >= E) return;
    int s, d;
    if (d_is64) {
        s = ei_w[2 * e];
        d = ei_w[2 * E + 2 * e];
    } else {
        s = ei_w[e];
        d = ei_w[E + e];
    }
    d_src[e] = s;
    d_dst[e] = d;
    atomicAdd(&d_deg[d], 1.0f);
}

// ------------------------------------------------- K2: GEMM + dinv scale (4x4 register-blocked)
// 256 threads/block, 128 rows/block. Thread (rl = tid>>3, cg = tid&7) computes
// rows {rl, rl+32, rl+64, rl+96} x cols [cg*4, cg*4+4). No shared memory:
// x row reads are warp-broadcast L1 hits (8 consecutive lanes share the addr),
// W (16KB) is L1-resident. 16 FFMA per 5 loads -> FMA-dominated mix.
__global__ void __launch_bounds__(256) k_gemm(const float* __restrict__ x,
                                              const float* __restrict__ W, int n) {
    int tid = threadIdx.x;
    int rl  = tid >> 3;       // 0..31
    int cg  = tid & 7;        // 0..7
    int rbase = blockIdx.x * 128;

    int rows[4];
    const float* xr[4];
#pragma unroll
    for (int m = 0; m < 4; m++) {
        rows[m] = rbase + rl + 32 * m;
        int rc = rows[m] < n ? rows[m] : (n - 1);   // clamp: safe load, guarded store
        xr[m] = x + (size_t)rc * IN_CH;
    }
    const float* Wc = W + cg * 4;

    float a[4][4];
#pragma unroll
    for (int m = 0; m < 4; m++)
#pragma unroll
        for (int c = 0; c < 4; c++) a[m][c] = 0.0f;

#pragma unroll 4
    for (int k = 0; k < IN_CH; k++) {
        float4 wv = *(const float4*)(Wc + k * OUT_CH);
#pragma unroll
        for (int m = 0; m < 4; m++) {
            float xv = __ldg(&xr[m][k]);
            a[m][0] += xv * wv.x;
            a[m][1] += xv * wv.y;
            a[m][2] += xv * wv.z;
            a[m][3] += xv * wv.w;
        }
    }

#pragma unroll
    for (int m = 0; m < 4; m++) {
        int row = rows[m];
        if (row < n) {
            float dinv = rsqrtf(d_deg[row] + 1.0f);   // +1 = self loop
            if (cg == 0) d_dinv[row] = dinv;
            float4 o = make_float4(a[m][0] * dinv, a[m][1] * dinv,
                                   a[m][2] * dinv, a[m][3] * dinv);
            int off = row * OUT_CH + cg * 4;
            *(float4*)&d_g[off] = o;
            *(float4*)&d_s[off] = o;   // accumulator starts with self-loop term
        }
    }
}

// ------------------------------------------------- K3: edge scatter
// 8 lanes per edge, 4 edges per warp; red.global.add.v4.f32 accumulation.
__global__ void k_scatter(int E) {
    int wid  = (blockIdx.x * blockDim.x + threadIdx.x) >> 5;
    int lane = threadIdx.x & 31;
    int grp  = lane >> 3;     // edge within warp
    int sub  = lane & 7;      // float4 slot within row
    int e = wid * 4 + grp;
    if (e >= E) return;
    int s = d_src[e];
    int d = d_dst[e];
    float4 v = *(const float4*)&d_g[s * OUT_CH + sub * 4];
    float* addr = &d_s[d * OUT_CH + sub * 4];
    asm volatile("red.global.add.v4.f32 [%0], {%1,%2,%3,%4};"
                 :: "l"(addr), "f"(v.x), "f"(v.y), "f"(v.z), "f"(v.w)
                 : "memory");
}

// ------------------------------------------------- K4: z = relu(dinv*s + b)
__global__ void k_activate(const float* __restrict__ b, int n) {
    int i = blockIdx.x * blockDim.x + threadIdx.x;
    if (i < n * OUT_CH) {
        int node = i >> 5;
        int c = i & 31;
        float v = d_dinv[node] * d_s[i] + b[c];
        d_z[i] = v > 0.0f ? v : 0.0f;
    }
}

// ------------------------------------------------- K5: decoder
__global__ void k_decode(float* __restrict__ out, int E) {
    int wid  = (blockIdx.x * blockDim.x + threadIdx.x) >> 5;
    int lane = threadIdx.x & 31;
    int grp  = lane >> 3;
    int sub  = lane & 7;
    int e = wid * 4 + grp;
    if (e >= E) return;
    int s = d_src[e];
    int d = d_dst[e];
    float4 a = *(const float4*)&d_z[s * OUT_CH + sub * 4];
    float4 c = *(const float4*)&d_z[d * OUT_CH + sub * 4];
    float p = a.x * c.x + a.y * c.y + a.z * c.z + a.w * c.w;
    p += __shfl_xor_sync(0xffffffffu, p, 4);
    p += __shfl_xor_sync(0xffffffffu, p, 2);
    p += __shfl_xor_sync(0xffffffffu, p, 1);
    if (sub == 0) out[e] = 1.0f / (1.0f + __expf(-p));
}

// ------------------------------------------------- launch
extern "C" void kernel_launch(void* const* d_in, const int* in_sizes, int n_in,
                              void* d_out, int out_size) {
    const float* x    = (const float*)d_in[0];
    const int*   ei_w = (const int*)d_in[1];   // edge_index as 32-bit words
    const float* W    = (const float*)d_in[2];
    const float* b    = (const float*)d_in[3];
    float* out = (float*)d_out;

    int n = in_sizes[0] / IN_CH;      // 100000
    int E = in_sizes[1] / 2;          // 1600000

    k_detect        <<<1, 32>>>(ei_w);
    k_zero          <<<(n + 255) / 256, 256>>>(n);
    k_convert_degree<<<(E + 255) / 256, 256>>>(ei_w, E);
    k_gemm          <<<(n + 127) / 128, 256>>>(x, W, n);
    {   // 8 threads per edge
        long long threads = (long long)E * 8;
        k_scatter<<<(int)((threads + 255) / 256), 256>>>(E);
    }
    k_activate      <<<(n * OUT_CH + 255) / 256, 256>>>(b, n);
    {
        long long threads = (long long)E * 8;
        k_decode<<<(int)((threads + 255) / 256), 256>>>(out, E);
    }
}

// round 6
// speedup vs baseline: 1.3674x; 1.2394x over previous
#include <cuda_runtime.h>
#include <stdint.h>

#define IN_CH   128
#define OUT_CH  32
#define MAX_N   100000
#define MAX_E   1600000

// Scratch (allocation-free rule: __device__ globals). 16B alignment is
// load-bearing: float4 loads + red.global.add.v4.f32 require it.
__device__ __align__(16) float d_deg [MAX_N];
__device__ __align__(16) float d_dinv[MAX_N];
__device__ __align__(16) float d_g   [MAX_N * OUT_CH];
__device__ __align__(16) float d_s   [MAX_N * OUT_CH];
__device__ __align__(16) float d_z   [MAX_N * OUT_CH];
__device__ int d_src[MAX_E];
__device__ int d_dst[MAX_E];
__device__ int d_is64;

// ------------------------------------------------- K_detect: int64 vs int32?
__global__ void k_detect(const int* __restrict__ ei_w) {
    if (threadIdx.x == 0) {
        int acc = 0;
        for (int t = 0; t < 64; t++) acc |= ei_w[2 * t + 1];
        d_is64 = (acc == 0) ? 1 : 0;
    }
}

// ------------------------------------------------- K0: zero deg
__global__ void k_zero(int n) {
    int i = blockIdx.x * blockDim.x + threadIdx.x;
    if (i < n) d_deg[i] = 0.0f;
}

// ------------------------------------------------- K1: convert + in-degree (fused)
__global__ void k_convert_degree(const int* __restrict__ ei_w, int E) {
    int e = blockIdx.x * blockDim.x + threadIdx.x;
    if (e >= E) return;
    int s, d;
    if (d_is64) {
        s = ei_w[2 * e];
        d = ei_w[2 * E + 2 * e];
    } else {
        s = ei_w[e];
        d = ei_w[E + e];
    }
    d_src[e] = s;
    d_dst[e] = d;
    atomicAdd(&d_deg[d], 1.0f);
}

// ------------------------------------------------- K2: GEMM + dinv scale
// 4x4 register-blocked, k vectorized by 4. Per 4-k chunk each thread issues
// 4 x-LDG.128 (broadcast across the 8 cg lanes of the warp) + 4 W-LDG.128
// (L1-resident) against 64 FFMA -> 8 FFMA per load (was 3.2).
__global__ void __launch_bounds__(256) k_gemm(const float* __restrict__ x,
                                              const float* __restrict__ W, int n) {
    int tid = threadIdx.x;
    int rl  = tid >> 3;       // 0..31
    int cg  = tid & 7;        // 0..7
    int rbase = blockIdx.x * 128;

    int rows[4];
    const float4* xr[4];
#pragma unroll
    for (int m = 0; m < 4; m++) {
        rows[m] = rbase + rl + 32 * m;
        int rc = rows[m] < n ? rows[m] : (n - 1);   // clamp: safe load, guarded store
        xr[m] = (const float4*)(x + (size_t)rc * IN_CH);
    }
    const float* Wc = W + cg * 4;

    float a[4][4];
#pragma unroll
    for (int m = 0; m < 4; m++)
#pragma unroll
        for (int c = 0; c < 4; c++) a[m][c] = 0.0f;

#pragma unroll 2
    for (int kc = 0; kc < IN_CH / 4; kc++) {
        float4 xv[4];
#pragma unroll
        for (int m = 0; m < 4; m++) xv[m] = xr[m][kc];
        float4 w0 = *(const float4*)(Wc + (kc * 4 + 0) * OUT_CH);
        float4 w1 = *(const float4*)(Wc + (kc * 4 + 1) * OUT_CH);
        float4 w2 = *(const float4*)(Wc + (kc * 4 + 2) * OUT_CH);
        float4 w3 = *(const float4*)(Wc + (kc * 4 + 3) * OUT_CH);
#pragma unroll
        for (int m = 0; m < 4; m++) {
            a[m][0] += xv[m].x * w0.x; a[m][1] += xv[m].x * w0.y;
            a[m][2] += xv[m].x * w0.z; a[m][3] += xv[m].x * w0.w;
            a[m][0] += xv[m].y * w1.x; a[m][1] += xv[m].y * w1.y;
            a[m][2] += xv[m].y * w1.z; a[m][3] += xv[m].y * w1.w;
            a[m][0] += xv[m].z * w2.x; a[m][1] += xv[m].z * w2.y;
            a[m][2] += xv[m].z * w2.z; a[m][3] += xv[m].z * w2.w;
            a[m][0] += xv[m].w * w3.x; a[m][1] += xv[m].w * w3.y;
            a[m][2] += xv[m].w * w3.z; a[m][3] += xv[m].w * w3.w;
        }
    }

#pragma unroll
    for (int m = 0; m < 4; m++) {
        int row = rows[m];
        if (row < n) {
            float dinv = rsqrtf(d_deg[row] + 1.0f);   // +1 = self loop
            if (cg == 0) d_dinv[row] = dinv;
            float4 o = make_float4(a[m][0] * dinv, a[m][1] * dinv,
                                   a[m][2] * dinv, a[m][3] * dinv);
            int off = row * OUT_CH + cg * 4;
            *(float4*)&d_g[off] = o;
            *(float4*)&d_s[off] = o;   // accumulator starts with self-loop term
        }
    }
}

// ------------------------------------------------- K3: edge scatter
// 8 lanes per edge, 4 edges per warp; red.global.add.v4.f32 accumulation.
__global__ void k_scatter(int E) {
    int wid  = (blockIdx.x * blockDim.x + threadIdx.x) >> 5;
    int lane = threadIdx.x & 31;
    int grp  = lane >> 3;     // edge within warp
    int sub  = lane & 7;      // float4 slot within row
    int e = wid * 4 + grp;
    if (e >= E) return;
    int s = d_src[e];
    int d = d_dst[e];
    float4 v = *(const float4*)&d_g[s * OUT_CH + sub * 4];
    float* addr = &d_s[d * OUT_CH + sub * 4];
    asm volatile("red.global.add.v4.f32 [%0], {%1,%2,%3,%4};"
                 :: "l"(addr), "f"(v.x), "f"(v.y), "f"(v.z), "f"(v.w)
                 : "memory");
}

// ------------------------------------------------- K4: z = relu(dinv*s + b)
__global__ void k_activate(const float* __restrict__ b, int n) {
    int i = blockIdx.x * blockDim.x + threadIdx.x;
    if (i < n * OUT_CH) {
        int node = i >> 5;
        int c = i & 31;
        float v = d_dinv[node] * d_s[i] + b[c];
        d_z[i] = v > 0.0f ? v : 0.0f;
    }
}

// ------------------------------------------------- K5: decoder
__global__ void k_decode(float* __restrict__ out, int E) {
    int wid  = (blockIdx.x * blockDim.x + threadIdx.x) >> 5;
    int lane = threadIdx.x & 31;
    int grp  = lane >> 3;
    int sub  = lane & 7;
    int e = wid * 4 + grp;
    if (e >= E) return;
    int s = d_src[e];
    int d = d_dst[e];
    float4 a = *(const float4*)&d_z[s * OUT_CH + sub * 4];
    float4 c = *(const float4*)&d_z[d * OUT_CH + sub * 4];
    float p = a.x * c.x + a.y * c.y + a.z * c.z + a.w * c.w;
    p += __shfl_xor_sync(0xffffffffu, p, 4);
    p += __shfl_xor_sync(0xffffffffu, p, 2);
    p += __shfl_xor_sync(0xffffffffu, p, 1);
    if (sub == 0) out[e] = 1.0f / (1.0f + __expf(-p));
}

// ------------------------------------------------- launch
extern "C" void kernel_launch(void* const* d_in, const int* in_sizes, int n_in,
                              void* d_out, int out_size) {
    const float* x    = (const float*)d_in[0];
    const int*   ei_w = (const int*)d_in[1];   // edge_index as 32-bit words
    const float* W    = (const float*)d_in[2];
    const float* b    = (const float*)d_in[3];
    float* out = (float*)d_out;

    int n = in_sizes[0] / IN_CH;      // 100000
    int E = in_sizes[1] / 2;          // 1600000

    k_detect        <<<1, 32>>>(ei_w);
    k_zero          <<<(n + 255) / 256, 256>>>(n);
    k_convert_degree<<<(E + 255) / 256, 256>>>(ei_w, E);
    k_gemm          <<<(n + 127) / 128, 256>>>(x, W, n);
    {   // 8 threads per edge
        long long threads = (long long)E * 8;
        k_scatter<<<(int)((threads + 255) / 256), 256>>>(E);
    }
    k_activate      <<<(n * OUT_CH + 255) / 256, 256>>>(b, n);
    {
        long long threads = (long long)E * 8;
        k_decode<<<(int)((threads + 255) / 256), 256>>>(out, E);
    }
}